// round 1
// baseline (speedup 1.0000x reference)
#include <cuda_runtime.h>

#define Bb 16
#define Cc 256
#define Hh 64
#define Ww 64
#define K9 2304        // C*9
#define EPSf 1e-5f

// ---------------- device scratch (no allocations allowed) ----------------
__device__ float g_S[3 * Bb * Cc * Ww];   // S[dy][(b*C+c)*W + w]
__device__ float g_wksum[K9];             // sum_c wk[c][c2][dy][dx]
__device__ float g_ksum[Bb * Ww];         // k_sum[b][w]
__device__ float g_G[Bb * K9];            // G[b][c2*9 + dy*3+dx]
__device__ float g_scores[Bb * Cc];       // softmax scores

// ---------------- K1: column sums of x (with top/bot corrections) --------
__global__ void k_colsum(const float* __restrict__ x) {
    int bc = blockIdx.x;          // b*C + c
    int w  = threadIdx.x;         // 0..63
    const float* p = x + ((size_t)bc * Hh) * Ww + w;
    float top = p[0];
    float sum = 0.f, last = 0.f;
    #pragma unroll 4
    for (int h = 0; h < Hh; ++h) { last = p[h * Ww]; sum += last; }
    g_S[0 * (Bb*Cc*Ww) + bc * Ww + w] = sum - last;  // dy=0: rows 0..H-2
    g_S[1 * (Bb*Cc*Ww) + bc * Ww + w] = sum;         // dy=1: full
    g_S[2 * (Bb*Cc*Ww) + bc * Ww + w] = sum - top;   // dy=2: rows 1..H-1
}

// ---------------- K2: wksum[t] = sum_c wk[c][t],  t = c2*9+j -------------
__global__ void k_wksum(const float* __restrict__ wk) {
    int t = blockIdx.x * blockDim.x + threadIdx.x;
    if (t >= K9) return;
    float s = 0.f;
    for (int c = 0; c < Cc; ++c) s += wk[(size_t)c * K9 + t];
    g_wksum[t] = s;
}

// ---------------- K3: k_sum[b][w] ----------------------------------------
__global__ void k_ksum() {
    __shared__ float wks[K9];
    __shared__ float Ssm[3][32][64];
    int b = blockIdx.x, w = threadIdx.x;   // 64 threads
    for (int i = w; i < K9; i += 64) wks[i] = g_wksum[i];
    float acc = 0.f;
    for (int c20 = 0; c20 < Cc; c20 += 32) {
        __syncthreads();
        for (int i = w; i < 3 * 32 * 64; i += 64) {
            int dy = i / (32 * 64); int r = i - dy * (32 * 64);
            int cc = r / 64;        int ww = r - cc * 64;
            Ssm[dy][cc][ww] = g_S[dy * (Bb*Cc*Ww) + (b * Cc + c20 + cc) * Ww + ww];
        }
        __syncthreads();
        for (int cc = 0; cc < 32; ++cc) {
            const float* wp = &wks[(c20 + cc) * 9];
            #pragma unroll
            for (int dy = 0; dy < 3; ++dy) {
                float sm1 = (w > 0)  ? Ssm[dy][cc][w - 1] : 0.f;
                float s0  =            Ssm[dy][cc][w];
                float sp1 = (w < 63) ? Ssm[dy][cc][w + 1] : 0.f;
                acc += wp[dy*3+0]*sm1 + wp[dy*3+1]*s0 + wp[dy*3+2]*sp1;
            }
        }
    }
    g_ksum[b * Ww + w] = acc;
}

// ---------------- K4: G[b][c2][dy][dx] = sum_w S_dy[..,w+dx-1]*ksum[b,w] -
__global__ void k_G() {
    int c2 = blockIdx.x, b = blockIdx.y;
    int j    = threadIdx.x >> 5;    // warp id 0..8  (288 threads)
    int lane = threadIdx.x & 31;
    int dy = j / 3, dx = j % 3;
    const float* Srow = &g_S[dy * (Bb*Cc*Ww) + (b * Cc + c2) * Ww];
    const float* kr   = &g_ksum[b * Ww];
    float acc = 0.f;
    for (int w = lane; w < Ww; w += 32) {
        int wp = w + dx - 1;
        if (wp >= 0 && wp < Ww) acc += Srow[wp] * kr[w];
    }
    #pragma unroll
    for (int o = 16; o; o >>= 1) acc += __shfl_xor_sync(0xffffffffu, acc, o);
    if (lane == 0) g_G[b * K9 + c2 * 9 + j] = acc;
}

// ---------------- K5: f_scores = wq @ G[b] / 32768, then softmax ---------
__global__ void k_scores(const float* __restrict__ wq) {
    __shared__ float Gs[K9];
    __shared__ float red[256];
    int b = blockIdx.x, c = threadIdx.x;   // 256 threads
    for (int i = c; i < K9; i += 256) Gs[i] = g_G[b * K9 + i];
    __syncthreads();
    const float* wr = wq + (size_t)c * K9;
    float acc = 0.f;
    #pragma unroll 8
    for (int k = 0; k < K9; ++k) acc += wr[k] * Gs[k];
    float f = acc * (1.0f / 32768.0f);     // / (sqrt(64) * 64*64)
    red[c] = f; __syncthreads();
    for (int s = 128; s; s >>= 1) { if (c < s) red[c] = fmaxf(red[c], red[c + s]); __syncthreads(); }
    float m = red[0]; __syncthreads();
    float e = expf(f - m);
    red[c] = e; __syncthreads();
    for (int s = 128; s; s >>= 1) { if (c < s) red[c] += red[c + s]; __syncthreads(); }
    g_scores[b * Cc + c] = e / red[0];
}

// ---------------- K6: fv = conv3x3(x, wv) fused with epilogue ------------
// block tile: b fixed, 4 h-rows, all 64 w, 64 c_out. 256 threads.
// thread tile: 8 c_out x 8 w pixels (one h row).
__global__ void __launch_bounds__(256, 2) k_conv(
    const float* __restrict__ x, const float* __restrict__ wv,
    const float* __restrict__ gamma, const float* __restrict__ beta,
    const float* __restrict__ rmean, const float* __restrict__ rvar,
    float* __restrict__ out)
{
    __shared__ float xs[8][6][66];   // [ci][row h0-1..h0+4][w -1..64]
    __shared__ float ws[64][8][9];   // [co][ci][3x3]

    int cout0 = blockIdx.x * 64;     // 4 c_out tiles
    int h0    = blockIdx.y * 4;      // 16 h tiles
    int b     = blockIdx.z;          // 16 batches
    int tid = threadIdx.x;
    int tx = tid & 7;                // w group: w0 = tx*8
    int ty = (tid >> 3) & 3;         // h row within tile
    int cz = tid >> 5;               // c_out group: 8 per group
    int w0 = tx * 8;

    float acc[8][8];
    #pragma unroll
    for (int i = 0; i < 8; ++i)
        #pragma unroll
        for (int j = 0; j < 8; ++j) acc[i][j] = 0.f;

    const float* xb = x + (size_t)b * Cc * Hh * Ww;

    for (int cin0 = 0; cin0 < Cc; cin0 += 8) {
        __syncthreads();
        // stage x tile: 8 ci x 6 rows x 66 cols (zero-padded halo)
        for (int idx = tid; idx < 8 * 6 * 66; idx += 256) {
            int ci = idx / 396; int rem = idx - ci * 396;
            int r = rem / 66;   int j = rem - r * 66;
            int gh = h0 - 1 + r, gw = j - 1;
            float v = 0.f;
            if (gh >= 0 && gh < Hh && gw >= 0 && gw < Ww)
                v = xb[((size_t)(cin0 + ci) * Hh + gh) * Ww + gw];
            xs[ci][r][j] = v;
        }
        // stage weights: 64 co x 8 ci x 9
        for (int idx = tid; idx < 64 * 8 * 9; idx += 256) {
            int co = idx / 72; int rem = idx - co * 72;
            int ci = rem / 9;  int j = rem - ci * 9;
            ws[co][ci][j] = wv[((size_t)(cout0 + co) * Cc + (cin0 + ci)) * 9 + j];
        }
        __syncthreads();

        for (int ci = 0; ci < 8; ++ci) {
            float xv[3][10];
            #pragma unroll
            for (int dy = 0; dy < 3; ++dy)
                #pragma unroll
                for (int k = 0; k < 10; ++k) xv[dy][k] = xs[ci][ty + dy][w0 + k];
            #pragma unroll
            for (int co = 0; co < 8; ++co) {
                float w9[9];
                #pragma unroll
                for (int j = 0; j < 9; ++j) w9[j] = ws[cz * 8 + co][ci][j];
                #pragma unroll
                for (int wi = 0; wi < 8; ++wi) {
                    float a = acc[co][wi];
                    #pragma unroll
                    for (int dy = 0; dy < 3; ++dy)
                        #pragma unroll
                        for (int dx = 0; dx < 3; ++dx)
                            a += w9[dy * 3 + dx] * xv[dy][wi + dx];
                    acc[co][wi] = a;
                }
            }
        }
    }

    // epilogue: r = scores*fv + x; BN (folded); ReLU
    int h = h0 + ty;
    #pragma unroll
    for (int co = 0; co < 8; ++co) {
        int c = cout0 + cz * 8 + co;
        float s     = g_scores[b * Cc + c];
        float scale = gamma[c] * rsqrtf(rvar[c] + EPSf);
        float bias  = beta[c] - rmean[c] * scale;
        const float* xr = xb + ((size_t)c * Hh + h) * Ww + w0;
        float* orow = out + (((size_t)b * Cc + c) * Hh + h) * Ww + w0;
        #pragma unroll
        for (int wi = 0; wi < 8; ++wi) {
            float r = s * acc[co][wi] + xr[wi];
            float o = r * scale + bias;
            orow[wi] = fmaxf(o, 0.f);
        }
    }
}

// ---------------- launch --------------------------------------------------
extern "C" void kernel_launch(void* const* d_in, const int* in_sizes, int n_in,
                              void* d_out, int out_size)
{
    const float* x     = (const float*)d_in[0];
    const float* wq    = (const float*)d_in[1];
    const float* wk    = (const float*)d_in[2];
    const float* wv    = (const float*)d_in[3];
    const float* gamma = (const float*)d_in[4];
    const float* beta  = (const float*)d_in[5];
    const float* rmean = (const float*)d_in[6];
    const float* rvar  = (const float*)d_in[7];
    float* out = (float*)d_out;
    (void)in_sizes; (void)n_in; (void)out_size;

    k_colsum<<<Bb * Cc, 64>>>(x);
    k_wksum<<<(K9 + 255) / 256, 256>>>(wk);
    k_ksum<<<Bb, 64>>>();
    k_G<<<dim3(Cc, Bb), 288>>>();
    k_scores<<<Bb, 256>>>(wq);
    k_conv<<<dim3(4, 16, 16), 256>>>(x, wv, gamma, beta, rmean, rvar, out);
}

// round 4
// speedup vs baseline: 2.9839x; 2.9839x over previous
#include <cuda_runtime.h>
#include <cuda_bf16.h>
#include <cstdint>

#define Bb 16
#define Cc 256
#define Hh 64
#define Ww 64
#define K9 2304        // C*9
#define EPSf 1e-5f

// ---------------- device scratch (no allocations allowed) ----------------
__device__ float g_S[3 * Bb * Cc * Ww];
__device__ float g_wksum[K9];
__device__ float g_ksum[Bb * Ww];
__device__ float g_G[Bb * K9];
__device__ float g_scores[Bb * Cc];
__device__ __nv_bfloat16 g_wpack[Cc * 9 * Cc];   // [co][j=dy*3+dx][ci]

// ---------------- K1..K5: scores pipeline (unchanged, proven) -----------
__global__ void k_colsum(const float* __restrict__ x) {
    int bc = blockIdx.x;
    int w  = threadIdx.x;
    const float* p = x + ((size_t)bc * Hh) * Ww + w;
    float top = p[0];
    float sum = 0.f, last = 0.f;
    #pragma unroll 4
    for (int h = 0; h < Hh; ++h) { last = p[h * Ww]; sum += last; }
    g_S[0 * (Bb*Cc*Ww) + bc * Ww + w] = sum - last;
    g_S[1 * (Bb*Cc*Ww) + bc * Ww + w] = sum;
    g_S[2 * (Bb*Cc*Ww) + bc * Ww + w] = sum - top;
}
__global__ void k_wksum(const float* __restrict__ wk) {
    int t = blockIdx.x * blockDim.x + threadIdx.x;
    if (t >= K9) return;
    float s = 0.f;
    for (int c = 0; c < Cc; ++c) s += wk[(size_t)c * K9 + t];
    g_wksum[t] = s;
}
__global__ void k_ksum() {
    __shared__ float wks[K9];
    __shared__ float Ssm[3][32][64];
    int b = blockIdx.x, w = threadIdx.x;
    for (int i = w; i < K9; i += 64) wks[i] = g_wksum[i];
    float acc = 0.f;
    for (int c20 = 0; c20 < Cc; c20 += 32) {
        __syncthreads();
        for (int i = w; i < 3 * 32 * 64; i += 64) {
            int dy = i / (32 * 64); int r = i - dy * (32 * 64);
            int cc = r / 64;        int ww = r - cc * 64;
            Ssm[dy][cc][ww] = g_S[dy * (Bb*Cc*Ww) + (b * Cc + c20 + cc) * Ww + ww];
        }
        __syncthreads();
        for (int cc = 0; cc < 32; ++cc) {
            const float* wp = &wks[(c20 + cc) * 9];
            #pragma unroll
            for (int dy = 0; dy < 3; ++dy) {
                float sm1 = (w > 0)  ? Ssm[dy][cc][w - 1] : 0.f;
                float s0  =            Ssm[dy][cc][w];
                float sp1 = (w < 63) ? Ssm[dy][cc][w + 1] : 0.f;
                acc += wp[dy*3+0]*sm1 + wp[dy*3+1]*s0 + wp[dy*3+2]*sp1;
            }
        }
    }
    g_ksum[b * Ww + w] = acc;
}
__global__ void k_G() {
    int c2 = blockIdx.x, b = blockIdx.y;
    int j    = threadIdx.x >> 5;
    int lane = threadIdx.x & 31;
    int dy = j / 3, dx = j % 3;
    const float* Srow = &g_S[dy * (Bb*Cc*Ww) + (b * Cc + c2) * Ww];
    const float* kr   = &g_ksum[b * Ww];
    float acc = 0.f;
    for (int w = lane; w < Ww; w += 32) {
        int wp = w + dx - 1;
        if (wp >= 0 && wp < Ww) acc += Srow[wp] * kr[w];
    }
    #pragma unroll
    for (int o = 16; o; o >>= 1) acc += __shfl_xor_sync(0xffffffffu, acc, o);
    if (lane == 0) g_G[b * K9 + c2 * 9 + j] = acc;
}
__global__ void k_scores(const float* __restrict__ wq) {
    __shared__ float Gs[K9];
    __shared__ float red[256];
    int b = blockIdx.x, c = threadIdx.x;
    for (int i = c; i < K9; i += 256) Gs[i] = g_G[b * K9 + i];
    __syncthreads();
    const float* wr = wq + (size_t)c * K9;
    float acc = 0.f;
    #pragma unroll 8
    for (int k = 0; k < K9; ++k) acc += wr[k] * Gs[k];
    float f = acc * (1.0f / 32768.0f);
    red[c] = f; __syncthreads();
    for (int s = 128; s; s >>= 1) { if (c < s) red[c] = fmaxf(red[c], red[c + s]); __syncthreads(); }
    float m = red[0]; __syncthreads();
    float e = expf(f - m);
    red[c] = e; __syncthreads();
    for (int s = 128; s; s >>= 1) { if (c < s) red[c] += red[c + s]; __syncthreads(); }
    g_scores[b * Cc + c] = e / red[0];
}

// ---------------- K-pre: pack wv -> bf16 [co][j][ci] ---------------------
__global__ void k_wpack(const float* __restrict__ wv) {
    int idx = blockIdx.x * blockDim.x + threadIdx.x;
    if (idx >= Cc * K9) return;
    int co = idx / K9; int r = idx - co * K9;
    int ci = r / 9;    int j = r - ci * 9;
    g_wpack[((size_t)co * 9 + j) * Cc + ci] = __float2bfloat16(wv[idx]);
}

// ======================= K6: mma.sync bf16 implicit GEMM =================
// CTA: 128 co x 256 pixels (4 h-rows x 64 w), 512 threads (16 warps 4x4).
// Warp tile: 32 co x 64 pixels. K = 2304 as 8 ci-chunks x (3 dy x 3 dx x 32 ci).
//
// smem: R[6 planes][96 k][64 w] bf16, k-stride 144B  -> 82944 B
//       As[128 co][288 k] bf16, row stride 592B      -> 75776 B
#define R_KSTRIDE 144
#define R_PLANE   (96 * R_KSTRIDE)       // 13824
#define R_BYTES   (6 * R_PLANE)          // 82944
#define A_STRIDE  592
#define OFF_AS    R_BYTES                // 16B aligned
#define SMEM_DYN  (R_BYTES + 128 * A_STRIDE)   // 158720

__device__ __forceinline__ uint32_t smem_u32(const void* p) {
    uint32_t a;
    asm("{ .reg .u64 t; cvta.to.shared.u64 t, %1; cvt.u32.u64 %0, t; }" : "=r"(a) : "l"(p));
    return a;
}
__device__ __forceinline__ void ldmat_x4(uint32_t* r, uint32_t addr) {
    asm volatile("ldmatrix.sync.aligned.m8n8.x4.shared.b16 {%0,%1,%2,%3}, [%4];"
                 : "=r"(r[0]), "=r"(r[1]), "=r"(r[2]), "=r"(r[3]) : "r"(addr));
}
__device__ __forceinline__ void ldmat_x4_t(uint32_t* r, uint32_t addr) {
    asm volatile("ldmatrix.sync.aligned.m8n8.x4.trans.shared.b16 {%0,%1,%2,%3}, [%4];"
                 : "=r"(r[0]), "=r"(r[1]), "=r"(r[2]), "=r"(r[3]) : "r"(addr));
}
__device__ __forceinline__ void mma16816(float* c, const uint32_t* a, uint32_t b0, uint32_t b1) {
    asm volatile("mma.sync.aligned.m16n8k16.row.col.f32.bf16.bf16.f32 "
                 "{%0,%1,%2,%3}, {%4,%5,%6,%7}, {%8,%9}, {%0,%1,%2,%3};"
                 : "+f"(c[0]), "+f"(c[1]), "+f"(c[2]), "+f"(c[3])
                 : "r"(a[0]), "r"(a[1]), "r"(a[2]), "r"(a[3]), "r"(b0), "r"(b1));
}

__global__ void __launch_bounds__(512, 1) k_conv(
    const float* __restrict__ x,
    const float* __restrict__ gamma, const float* __restrict__ beta,
    const float* __restrict__ rmean, const float* __restrict__ rvar,
    float* __restrict__ out)
{
    extern __shared__ __align__(128) char smem[];
    uint32_t sR  = smem_u32(smem);
    uint32_t sAs = sR + OFF_AS;

    int tid = threadIdx.x;
    int l   = tid & 31;
    int wm  = (tid >> 5) & 3;        // warp co group (co = wm*32 ..)
    int wp  = tid >> 7;              // warp pixel row (0..3)

    int co0 = blockIdx.x * 128;      // 0 or 128
    int b   = blockIdx.y >> 4;
    int h0  = (blockIdx.y & 15) << 2;

    const float* xb = x + (size_t)b * Cc * Hh * Ww;

    // per-lane ldmatrix address components
    uint32_t aBase = sAs + (uint32_t)(wm * 32 + (l & 15)) * A_STRIDE + ((l >> 4) * 8) * 2;
    uint32_t kLane = (uint32_t)(((l >> 3) & 1) * 8 + (l & 7));
    uint32_t wLane = (uint32_t)((l >> 4) * 8);
    uint32_t bBase = sR + kLane * R_KSTRIDE + wLane * 2;

    float acc[2][8][4];
    #pragma unroll
    for (int i = 0; i < 2; ++i)
        #pragma unroll
        for (int j = 0; j < 8; ++j)
            #pragma unroll
            for (int q = 0; q < 4; ++q) acc[i][j][q] = 0.f;

    const int wgrp = tid >> 6;       // 0..7  (staging R: (r,cl) groups)
    const int wlo  = tid & 63;       // staging w

    for (int chunk = 0; chunk < 8; ++chunk) {
        int ci0 = chunk * 32;
        __syncthreads();   // previous iteration's ldmatrix reads complete

        // ---- stage R: 6 rows x 32 ci x 64 w, replicated to 3 dx shifts
        #pragma unroll 4
        for (int it = 0; it < 24; ++it) {
            int i  = it * 8 + wgrp;          // 0..191
            int r  = i >> 5;                 // 0..5
            int cl = i & 31;
            int h  = h0 - 1 + r;
            float v = 0.f;
            if (h >= 0 && h < Hh)
                v = xb[((size_t)(ci0 + cl) * Hh + h) * Ww + wlo];
            uint16_t bv; { __nv_bfloat16 t = __float2bfloat16(v);
                           bv = *reinterpret_cast<uint16_t*>(&t); }
            char* plane = smem + r * R_PLANE;
            // dx=0 -> w+1 ; dx=1 -> w ; dx=2 -> w-1
            if (wlo < 63)
                *reinterpret_cast<uint16_t*>(plane + (cl)      * R_KSTRIDE + (wlo + 1) * 2) = bv;
            *reinterpret_cast<uint16_t*>(plane + (32 + cl) * R_KSTRIDE + wlo * 2) = bv;
            if (wlo > 0)
                *reinterpret_cast<uint16_t*>(plane + (64 + cl) * R_KSTRIDE + (wlo - 1) * 2) = bv;
        }
        // edge zeros: (dx=0, w=0), (dx=2, w=63)
        if (tid < 384) {
            int r  = tid / 64;
            int cl = (tid % 64) >> 1;
            char* plane = smem + r * R_PLANE;
            if (tid & 1)
                *reinterpret_cast<uint16_t*>(plane + (64 + cl) * R_KSTRIDE + 63 * 2) = 0;
            else
                *reinterpret_cast<uint16_t*>(plane + (cl) * R_KSTRIDE) = 0;
        }

        // ---- stage As: 128 co x 288 k  (k = dy*96 + dx*32 + cl)
        const __nv_bfloat16* wpk = g_wpack;
        #pragma unroll 2
        for (int it = 0; it < 18; ++it) {
            int idx = it * 512 + tid;        // 0..9215, each = 4 bf16
            int co  = idx / 72;
            int rem = idx - co * 72;
            int j   = rem >> 3;              // 0..8
            int q   = rem & 7;               // cl = 4q
            int dy = j / 3, dx = j - dy * 3;
            const uint2 v = *reinterpret_cast<const uint2*>(
                wpk + (((size_t)(co0 + co) * 9 + j) * Cc + ci0 + 4 * q));
            *reinterpret_cast<uint2*>(smem + OFF_AS + co * A_STRIDE
                                      + (dy * 96 + dx * 32 + 4 * q) * 2) = v;
        }
        __syncthreads();

        // ---- MMA: 3 dy x 6 ksteps of 16
        #pragma unroll
        for (int dy = 0; dy < 3; ++dy) {
            uint32_t bPlane = bBase + (uint32_t)(wp + dy) * R_PLANE;
            #pragma unroll
            for (int ks = 0; ks < 6; ++ks) {
                uint32_t a[2][4];
                uint32_t aAddr = aBase + (uint32_t)(dy * 96 + ks * 16) * 2;
                ldmat_x4(a[0], aAddr);
                ldmat_x4(a[1], aAddr + 16u * A_STRIDE);
                uint32_t bf[4][4];
                uint32_t bAddr = bPlane + (uint32_t)(ks * 16) * R_KSTRIDE;
                #pragma unroll
                for (int g = 0; g < 4; ++g)
                    ldmat_x4_t(bf[g], bAddr + (uint32_t)g * 32);
                #pragma unroll
                for (int mf = 0; mf < 2; ++mf)
                    #pragma unroll
                    for (int nf = 0; nf < 8; ++nf)
                        mma16816(acc[mf][nf], a[mf],
                                 bf[nf >> 1][(nf & 1) * 2], bf[nf >> 1][(nf & 1) * 2 + 1]);
            }
        }
    }

    // ---- epilogue: relu((scores*fv + x)*scale + bias)
    int h = h0 + wp;
    #pragma unroll
    for (int mf = 0; mf < 2; ++mf) {
        int coA = co0 + wm * 32 + mf * 16 + (l >> 2);
        int coB = coA + 8;
        float sA = g_scores[b * Cc + coA];
        float sB = g_scores[b * Cc + coB];
        float scA = gamma[coA] * rsqrtf(rvar[coA] + EPSf);
        float scB = gamma[coB] * rsqrtf(rvar[coB] + EPSf);
        float biA = beta[coA] - rmean[coA] * scA;
        float biB = beta[coB] - rmean[coB] * scB;
        const float* xrA = xb + ((size_t)coA * Hh + h) * Ww;
        const float* xrB = xb + ((size_t)coB * Hh + h) * Ww;
        float* oA = out + (((size_t)b * Cc + coA) * Hh + h) * Ww;
        float* oB = out + (((size_t)b * Cc + coB) * Hh + h) * Ww;
        #pragma unroll
        for (int nf = 0; nf < 8; ++nf) {
            int w = nf * 8 + (l & 3) * 2;
            float2 xvA = *reinterpret_cast<const float2*>(xrA + w);
            float2 xvB = *reinterpret_cast<const float2*>(xrB + w);
            float2 o0, o1;
            o0.x = fmaxf((sA * acc[mf][nf][0] + xvA.x) * scA + biA, 0.f);
            o0.y = fmaxf((sA * acc[mf][nf][1] + xvA.y) * scA + biA, 0.f);
            o1.x = fmaxf((sB * acc[mf][nf][2] + xvB.x) * scB + biB, 0.f);
            o1.y = fmaxf((sB * acc[mf][nf][3] + xvB.y) * scB + biB, 0.f);
            *reinterpret_cast<float2*>(oA + w) = o0;
            *reinterpret_cast<float2*>(oB + w) = o1;
        }
    }
}

// ---------------- launch --------------------------------------------------
extern "C" void kernel_launch(void* const* d_in, const int* in_sizes, int n_in,
                              void* d_out, int out_size)
{
    const float* x     = (const float*)d_in[0];
    const float* wq    = (const float*)d_in[1];
    const float* wk    = (const float*)d_in[2];
    const float* wv    = (const float*)d_in[3];
    const float* gamma = (const float*)d_in[4];
    const float* beta  = (const float*)d_in[5];
    const float* rmean = (const float*)d_in[6];
    const float* rvar  = (const float*)d_in[7];
    float* out = (float*)d_out;
    (void)in_sizes; (void)n_in; (void)out_size;

    cudaFuncSetAttribute(k_conv, cudaFuncAttributeMaxDynamicSharedMemorySize, SMEM_DYN);

    k_colsum<<<Bb * Cc, 64>>>(x);
    k_wksum<<<(K9 + 255) / 256, 256>>>(wk);
    k_wpack<<<(Cc * K9 + 255) / 256, 256>>>(wv);
    k_ksum<<<Bb, 64>>>();
    k_G<<<dim3(Cc, Bb), 288>>>();
    k_scores<<<Bb, 256>>>(wq);
    k_conv<<<dim3(2, 256), 512, SMEM_DYN>>>(x, gamma, beta, rmean, rvar, out);
}

// round 5
// speedup vs baseline: 5.3543x; 1.7944x over previous
#include <cuda_runtime.h>
#include <cuda_bf16.h>
#include <cstdint>

#define Bb 16
#define Cc 256
#define Hh 64
#define Ww 64
#define K9 2304        // C*9
#define EPSf 1e-5f

// ---------------- device scratch (no allocations allowed) ----------------
__device__ float g_S[3 * Bb * Cc * Ww];
__device__ float g_wksum[K9];
__device__ float g_ksum[Bb * Ww];
__device__ float g_G[Bb * K9];
__device__ float g_fs[Bb * Cc];
__device__ float g_scores[Bb * Cc];
__device__ __nv_bfloat16 g_wpack[Cc * 9 * Cc];   // [co][j=dy*3+dx][ci]

// ---------------- K1: column sums of x -----------------------------------
__global__ void k_colsum(const float* __restrict__ x) {
    int bc = blockIdx.x;
    int w  = threadIdx.x;
    const float* p = x + ((size_t)bc * Hh) * Ww + w;
    float top = p[0];
    float sum = 0.f, last = 0.f;
    #pragma unroll 8
    for (int h = 0; h < Hh; ++h) { last = p[h * Ww]; sum += last; }
    g_S[0 * (Bb*Cc*Ww) + bc * Ww + w] = sum - last;
    g_S[1 * (Bb*Cc*Ww) + bc * Ww + w] = sum;
    g_S[2 * (Bb*Cc*Ww) + bc * Ww + w] = sum - top;
}

// ---------------- K2: wksum[t] = sum_c wk[c][t] --------------------------
__global__ void k_wksum(const float* __restrict__ wk) {
    int t = blockIdx.x * blockDim.x + threadIdx.x;
    if (t >= K9) return;
    float s = 0.f;
    #pragma unroll 16
    for (int c = 0; c < Cc; ++c) s += wk[(size_t)c * K9 + t];
    g_wksum[t] = s;
}

// ---------------- K3: k_sum[b][w] — 1024 blocks x 256 threads ------------
__global__ void k_ksum() {
    int w = blockIdx.x, b = blockIdx.y;
    int c2 = threadIdx.x;                 // 256 threads
    const float* wp = &g_wksum[c2 * 9];
    float acc = 0.f;
    #pragma unroll
    for (int dy = 0; dy < 3; ++dy) {
        const float* Srow = &g_S[dy * (Bb*Cc*Ww) + (b * Cc + c2) * Ww];
        #pragma unroll
        for (int dx = 0; dx < 3; ++dx) {
            int ws = w + dx - 1;
            if (ws >= 0 && ws < Ww) acc += wp[dy*3+dx] * Srow[ws];
        }
    }
    #pragma unroll
    for (int o = 16; o; o >>= 1) acc += __shfl_xor_sync(0xffffffffu, acc, o);
    __shared__ float red[8];
    if ((c2 & 31) == 0) red[c2 >> 5] = acc;
    __syncthreads();
    if (c2 == 0) {
        float s = 0.f;
        #pragma unroll
        for (int i = 0; i < 8; ++i) s += red[i];
        g_ksum[b * Ww + w] = s;
    }
}

// ---------------- K4: G[b][c2][dy][dx] -----------------------------------
__global__ void k_G() {
    int c2 = blockIdx.x, b = blockIdx.y;
    int j    = threadIdx.x >> 5;
    int lane = threadIdx.x & 31;
    int dy = j / 3, dx = j % 3;
    const float* Srow = &g_S[dy * (Bb*Cc*Ww) + (b * Cc + c2) * Ww];
    const float* kr   = &g_ksum[b * Ww];
    float acc = 0.f;
    for (int w = lane; w < Ww; w += 32) {
        int wp = w + dx - 1;
        if (wp >= 0 && wp < Ww) acc += Srow[wp] * kr[w];
    }
    #pragma unroll
    for (int o = 16; o; o >>= 1) acc += __shfl_xor_sync(0xffffffffu, acc, o);
    if (lane == 0) g_G[b * K9 + c2 * 9 + j] = acc;
}

// ---------------- K5a: f_scores[b][co] = wq[co] . G[b] / 32768 -----------
// grid = 256 (one block per co), 256 threads = 16 k-segments x 16 batches
__global__ void k_fscore(const float* __restrict__ wq) {
    __shared__ float wrow[K9];
    __shared__ float part[16][17];
    int co = blockIdx.x, tid = threadIdx.x;
    for (int i = tid; i < K9; i += 256) wrow[i] = wq[(size_t)co * K9 + i];
    __syncthreads();
    int b   = tid & 15;
    int seg = tid >> 4;                    // 16 segments of 144
    const float* Gb = &g_G[b * K9 + seg * 144];
    const float* wr = &wrow[seg * 144];
    float acc = 0.f;
    #pragma unroll 16
    for (int k = 0; k < 144; ++k) acc += wr[k] * Gb[k];
    part[seg][b] = acc;
    __syncthreads();
    if (tid < 16) {
        float s = 0.f;
        #pragma unroll
        for (int i = 0; i < 16; ++i) s += part[i][tid];
        g_fs[tid * Cc + co] = s * (1.0f / 32768.0f);
    }
}

// ---------------- K5b: softmax over channels -----------------------------
__global__ void k_softmax() {
    __shared__ float red[256];
    int b = blockIdx.x, c = threadIdx.x;
    float f = g_fs[b * Cc + c];
    red[c] = f; __syncthreads();
    for (int s = 128; s; s >>= 1) { if (c < s) red[c] = fmaxf(red[c], red[c + s]); __syncthreads(); }
    float m = red[0]; __syncthreads();
    float e = expf(f - m);
    red[c] = e; __syncthreads();
    for (int s = 128; s; s >>= 1) { if (c < s) red[c] += red[c + s]; __syncthreads(); }
    g_scores[b * Cc + c] = e / red[0];
}

// ---------------- K-pre: pack wv -> bf16 [co][j][ci] ---------------------
__global__ void k_wpack(const float* __restrict__ wv) {
    int idx = blockIdx.x * blockDim.x + threadIdx.x;
    if (idx >= Cc * K9) return;
    int co = idx / K9; int r = idx - co * K9;
    int ci = r / 9;    int j = r - ci * 9;
    g_wpack[((size_t)co * 9 + j) * Cc + ci] = __float2bfloat16(wv[idx]);
}

// ======================= K6: mma.sync bf16 implicit GEMM =================
// (unchanged from Round 4 — passed at rel_err 9.3e-6)
#define R_KSTRIDE 144
#define R_PLANE   (96 * R_KSTRIDE)       // 13824
#define R_BYTES   (6 * R_PLANE)          // 82944
#define A_STRIDE  592
#define OFF_AS    R_BYTES
#define SMEM_DYN  (R_BYTES + 128 * A_STRIDE)   // 158720

__device__ __forceinline__ uint32_t smem_u32(const void* p) {
    uint32_t a;
    asm("{ .reg .u64 t; cvta.to.shared.u64 t, %1; cvt.u32.u64 %0, t; }" : "=r"(a) : "l"(p));
    return a;
}
__device__ __forceinline__ void ldmat_x4(uint32_t* r, uint32_t addr) {
    asm volatile("ldmatrix.sync.aligned.m8n8.x4.shared.b16 {%0,%1,%2,%3}, [%4];"
                 : "=r"(r[0]), "=r"(r[1]), "=r"(r[2]), "=r"(r[3]) : "r"(addr));
}
__device__ __forceinline__ void ldmat_x4_t(uint32_t* r, uint32_t addr) {
    asm volatile("ldmatrix.sync.aligned.m8n8.x4.trans.shared.b16 {%0,%1,%2,%3}, [%4];"
                 : "=r"(r[0]), "=r"(r[1]), "=r"(r[2]), "=r"(r[3]) : "r"(addr));
}
__device__ __forceinline__ void mma16816(float* c, const uint32_t* a, uint32_t b0, uint32_t b1) {
    asm volatile("mma.sync.aligned.m16n8k16.row.col.f32.bf16.bf16.f32 "
                 "{%0,%1,%2,%3}, {%4,%5,%6,%7}, {%8,%9}, {%0,%1,%2,%3};"
                 : "+f"(c[0]), "+f"(c[1]), "+f"(c[2]), "+f"(c[3])
                 : "r"(a[0]), "r"(a[1]), "r"(a[2]), "r"(a[3]), "r"(b0), "r"(b1));
}

__global__ void __launch_bounds__(512, 1) k_conv(
    const float* __restrict__ x,
    const float* __restrict__ gamma, const float* __restrict__ beta,
    const float* __restrict__ rmean, const float* __restrict__ rvar,
    float* __restrict__ out)
{
    extern __shared__ __align__(128) char smem[];
    uint32_t sR  = smem_u32(smem);
    uint32_t sAs = sR + OFF_AS;

    int tid = threadIdx.x;
    int l   = tid & 31;
    int wm  = (tid >> 5) & 3;
    int wp  = tid >> 7;

    int co0 = blockIdx.x * 128;
    int b   = blockIdx.y >> 4;
    int h0  = (blockIdx.y & 15) << 2;

    const float* xb = x + (size_t)b * Cc * Hh * Ww;

    uint32_t aBase = sAs + (uint32_t)(wm * 32 + (l & 15)) * A_STRIDE + ((l >> 4) * 8) * 2;
    uint32_t kLane = (uint32_t)(((l >> 3) & 1) * 8 + (l & 7));
    uint32_t wLane = (uint32_t)((l >> 4) * 8);
    uint32_t bBase = sR + kLane * R_KSTRIDE + wLane * 2;

    float acc[2][8][4];
    #pragma unroll
    for (int i = 0; i < 2; ++i)
        #pragma unroll
        for (int j = 0; j < 8; ++j)
            #pragma unroll
            for (int q = 0; q < 4; ++q) acc[i][j][q] = 0.f;

    const int wgrp = tid >> 6;
    const int wlo  = tid & 63;

    for (int chunk = 0; chunk < 8; ++chunk) {
        int ci0 = chunk * 32;
        __syncthreads();

        #pragma unroll 4
        for (int it = 0; it < 24; ++it) {
            int i  = it * 8 + wgrp;
            int r  = i >> 5;
            int cl = i & 31;
            int h  = h0 - 1 + r;
            float v = 0.f;
            if (h >= 0 && h < Hh)
                v = xb[((size_t)(ci0 + cl) * Hh + h) * Ww + wlo];
            uint16_t bv; { __nv_bfloat16 t = __float2bfloat16(v);
                           bv = *reinterpret_cast<uint16_t*>(&t); }
            char* plane = smem + r * R_PLANE;
            if (wlo < 63)
                *reinterpret_cast<uint16_t*>(plane + (cl)      * R_KSTRIDE + (wlo + 1) * 2) = bv;
            *reinterpret_cast<uint16_t*>(plane + (32 + cl) * R_KSTRIDE + wlo * 2) = bv;
            if (wlo > 0)
                *reinterpret_cast<uint16_t*>(plane + (64 + cl) * R_KSTRIDE + (wlo - 1) * 2) = bv;
        }
        if (tid < 384) {
            int r  = tid / 64;
            int cl = (tid % 64) >> 1;
            char* plane = smem + r * R_PLANE;
            if (tid & 1)
                *reinterpret_cast<uint16_t*>(plane + (64 + cl) * R_KSTRIDE + 63 * 2) = 0;
            else
                *reinterpret_cast<uint16_t*>(plane + (cl) * R_KSTRIDE) = 0;
        }

        const __nv_bfloat16* wpk = g_wpack;
        #pragma unroll 2
        for (int it = 0; it < 18; ++it) {
            int idx = it * 512 + tid;
            int co  = idx / 72;
            int rem = idx - co * 72;
            int j   = rem >> 3;
            int q   = rem & 7;
            int dy = j / 3, dx = j - dy * 3;
            const uint2 v = *reinterpret_cast<const uint2*>(
                wpk + (((size_t)(co0 + co) * 9 + j) * Cc + ci0 + 4 * q));
            *reinterpret_cast<uint2*>(smem + OFF_AS + co * A_STRIDE
                                      + (dy * 96 + dx * 32 + 4 * q) * 2) = v;
        }
        __syncthreads();

        #pragma unroll
        for (int dy = 0; dy < 3; ++dy) {
            uint32_t bPlane = bBase + (uint32_t)(wp + dy) * R_PLANE;
            #pragma unroll
            for (int ks = 0; ks < 6; ++ks) {
                uint32_t a[2][4];
                uint32_t aAddr = aBase + (uint32_t)(dy * 96 + ks * 16) * 2;
                ldmat_x4(a[0], aAddr);
                ldmat_x4(a[1], aAddr + 16u * A_STRIDE);
                uint32_t bf[4][4];
                uint32_t bAddr = bPlane + (uint32_t)(ks * 16) * R_KSTRIDE;
                #pragma unroll
                for (int g = 0; g < 4; ++g)
                    ldmat_x4_t(bf[g], bAddr + (uint32_t)g * 32);
                #pragma unroll
                for (int mf = 0; mf < 2; ++mf)
                    #pragma unroll
                    for (int nf = 0; nf < 8; ++nf)
                        mma16816(acc[mf][nf], a[mf],
                                 bf[nf >> 1][(nf & 1) * 2], bf[nf >> 1][(nf & 1) * 2 + 1]);
            }
        }
    }

    int h = h0 + wp;
    #pragma unroll
    for (int mf = 0; mf < 2; ++mf) {
        int coA = co0 + wm * 32 + mf * 16 + (l >> 2);
        int coB = coA + 8;
        float sA = g_scores[b * Cc + coA];
        float sB = g_scores[b * Cc + coB];
        float scA = gamma[coA] * rsqrtf(rvar[coA] + EPSf);
        float scB = gamma[coB] * rsqrtf(rvar[coB] + EPSf);
        float biA = beta[coA] - rmean[coA] * scA;
        float biB = beta[coB] - rmean[coB] * scB;
        const float* xrA = xb + ((size_t)coA * Hh + h) * Ww;
        const float* xrB = xb + ((size_t)coB * Hh + h) * Ww;
        float* oA = out + (((size_t)b * Cc + coA) * Hh + h) * Ww;
        float* oB = out + (((size_t)b * Cc + coB) * Hh + h) * Ww;
        #pragma unroll
        for (int nf = 0; nf < 8; ++nf) {
            int w = nf * 8 + (l & 3) * 2;
            float2 xvA = *reinterpret_cast<const float2*>(xrA + w);
            float2 xvB = *reinterpret_cast<const float2*>(xrB + w);
            float2 o0, o1;
            o0.x = fmaxf((sA * acc[mf][nf][0] + xvA.x) * scA + biA, 0.f);
            o0.y = fmaxf((sA * acc[mf][nf][1] + xvA.y) * scA + biA, 0.f);
            o1.x = fmaxf((sB * acc[mf][nf][2] + xvB.x) * scB + biB, 0.f);
            o1.y = fmaxf((sB * acc[mf][nf][3] + xvB.y) * scB + biB, 0.f);
            *reinterpret_cast<float2*>(oA + w) = o0;
            *reinterpret_cast<float2*>(oB + w) = o1;
        }
    }
}

// ---------------- launch --------------------------------------------------
extern "C" void kernel_launch(void* const* d_in, const int* in_sizes, int n_in,
                              void* d_out, int out_size)
{
    const float* x     = (const float*)d_in[0];
    const float* wq    = (const float*)d_in[1];
    const float* wk    = (const float*)d_in[2];
    const float* wv    = (const float*)d_in[3];
    const float* gamma = (const float*)d_in[4];
    const float* beta  = (const float*)d_in[5];
    const float* rmean = (const float*)d_in[6];
    const float* rvar  = (const float*)d_in[7];
    float* out = (float*)d_out;
    (void)in_sizes; (void)n_in; (void)out_size;

    cudaFuncSetAttribute(k_conv, cudaFuncAttributeMaxDynamicSharedMemorySize, SMEM_DYN);

    k_colsum<<<Bb * Cc, 64>>>(x);
    k_wksum<<<(K9 + 255) / 256, 256>>>(wk);
    k_wpack<<<(Cc * K9 + 255) / 256, 256>>>(wv);
    k_ksum<<<dim3(Ww, Bb), 256>>>();
    k_G<<<dim3(Cc, Bb), 288>>>();
    k_fscore<<<Cc, 256>>>(wq);
    k_softmax<<<Bb, 256>>>();
    k_conv<<<dim3(2, 256), 512, SMEM_DYN>>>(x, gamma, beta, rmean, rvar, out);
}

// round 6
// speedup vs baseline: 7.7673x; 1.4507x over previous
#include <cuda_runtime.h>
#include <cuda_bf16.h>
#include <cstdint>

#define Bb 16
#define Cc 256
#define Hh 64
#define Ww 64
#define K9 2304        // C*9
#define EPSf 1e-5f

// ---------------- device scratch (no allocations allowed) ----------------
__device__ float g_S[3 * Bb * Cc * Ww];
__device__ float g_wksum[K9];
__device__ float g_ksum[Bb * Ww];
__device__ float g_G[Bb * K9];
__device__ float g_fs[Bb * Cc];
__device__ float g_scores[Bb * Cc];
__device__ __nv_bfloat16 g_xbf[Bb * Cc * Hh * Ww];        // x in bf16, NCHW
__device__ __nv_bfloat16 g_wpk2[2 * 16 * 128 * 144];      // [half][chunk][co_l][k=dy*48+dx*16+cl]

// ---------------- K1: column sums of x + bf16 prepack (fused) ------------
__global__ void k_colsum(const float* __restrict__ x) {
    int bc = blockIdx.x;
    int w  = threadIdx.x;
    const float* p = x + ((size_t)bc * Hh) * Ww + w;
    __nv_bfloat16* xo = g_xbf + ((size_t)bc * Hh) * Ww + w;
    float top = p[0];
    float sum = 0.f, last = 0.f;
    #pragma unroll 8
    for (int h = 0; h < Hh; ++h) {
        last = p[h * Ww];
        sum += last;
        xo[h * Ww] = __float2bfloat16(last);
    }
    g_S[0 * (Bb*Cc*Ww) + bc * Ww + w] = sum - last;
    g_S[1 * (Bb*Cc*Ww) + bc * Ww + w] = sum;
    g_S[2 * (Bb*Cc*Ww) + bc * Ww + w] = sum - top;
}

// ---------------- K2: wksum[t] = sum_c wk[c][t] --------------------------
__global__ void k_wksum(const float* __restrict__ wk) {
    int t = blockIdx.x * blockDim.x + threadIdx.x;
    if (t >= K9) return;
    float s = 0.f;
    #pragma unroll 16
    for (int c = 0; c < Cc; ++c) s += wk[(size_t)c * K9 + t];
    g_wksum[t] = s;
}

// ---------------- K3: k_sum[b][w] ----------------------------------------
__global__ void k_ksum() {
    int w = blockIdx.x, b = blockIdx.y;
    int c2 = threadIdx.x;
    const float* wp = &g_wksum[c2 * 9];
    float acc = 0.f;
    #pragma unroll
    for (int dy = 0; dy < 3; ++dy) {
        const float* Srow = &g_S[dy * (Bb*Cc*Ww) + (b * Cc + c2) * Ww];
        #pragma unroll
        for (int dx = 0; dx < 3; ++dx) {
            int ws = w + dx - 1;
            if (ws >= 0 && ws < Ww) acc += wp[dy*3+dx] * Srow[ws];
        }
    }
    #pragma unroll
    for (int o = 16; o; o >>= 1) acc += __shfl_xor_sync(0xffffffffu, acc, o);
    __shared__ float red[8];
    if ((c2 & 31) == 0) red[c2 >> 5] = acc;
    __syncthreads();
    if (c2 == 0) {
        float s = 0.f;
        #pragma unroll
        for (int i = 0; i < 8; ++i) s += red[i];
        g_ksum[b * Ww + w] = s;
    }
}

// ---------------- K4: G[b][c2][dy][dx] -----------------------------------
__global__ void k_G() {
    int c2 = blockIdx.x, b = blockIdx.y;
    int j    = threadIdx.x >> 5;
    int lane = threadIdx.x & 31;
    int dy = j / 3, dx = j % 3;
    const float* Srow = &g_S[dy * (Bb*Cc*Ww) + (b * Cc + c2) * Ww];
    const float* kr   = &g_ksum[b * Ww];
    float acc = 0.f;
    for (int w = lane; w < Ww; w += 32) {
        int wp = w + dx - 1;
        if (wp >= 0 && wp < Ww) acc += Srow[wp] * kr[w];
    }
    #pragma unroll
    for (int o = 16; o; o >>= 1) acc += __shfl_xor_sync(0xffffffffu, acc, o);
    if (lane == 0) g_G[b * K9 + c2 * 9 + j] = acc;
}

// ---------------- K5a: f_scores[b][co] -----------------------------------
__global__ void k_fscore(const float* __restrict__ wq) {
    __shared__ float wrow[K9];
    __shared__ float part[16][17];
    int co = blockIdx.x, tid = threadIdx.x;
    for (int i = tid; i < K9; i += 256) wrow[i] = wq[(size_t)co * K9 + i];
    __syncthreads();
    int b   = tid & 15;
    int seg = tid >> 4;
    const float* Gb = &g_G[b * K9 + seg * 144];
    const float* wr = &wrow[seg * 144];
    float acc = 0.f;
    #pragma unroll 16
    for (int k = 0; k < 144; ++k) acc += wr[k] * Gb[k];
    part[seg][b] = acc;
    __syncthreads();
    if (tid < 16) {
        float s = 0.f;
        #pragma unroll
        for (int i = 0; i < 16; ++i) s += part[i][tid];
        g_fs[tid * Cc + co] = s * (1.0f / 32768.0f);
    }
}

// ---------------- K5b: softmax over channels -----------------------------
__global__ void k_softmax() {
    __shared__ float red[256];
    int b = blockIdx.x, c = threadIdx.x;
    float f = g_fs[b * Cc + c];
    red[c] = f; __syncthreads();
    for (int s = 128; s; s >>= 1) { if (c < s) red[c] = fmaxf(red[c], red[c + s]); __syncthreads(); }
    float m = red[0]; __syncthreads();
    float e = expf(f - m);
    red[c] = e; __syncthreads();
    for (int s = 128; s; s >>= 1) { if (c < s) red[c] += red[c + s]; __syncthreads(); }
    g_scores[b * Cc + c] = e / red[0];
}

// ---------------- K-pre: pack wv -> bf16 [half][chunk][co_l][k] ----------
// k = dy*48 + dx*16 + cl ; ci = chunk*16 + cl ; co = half*128 + co_l
__global__ void k_wpack2(const float* __restrict__ wv) {
    int t = blockIdx.x * blockDim.x + threadIdx.x;
    if (t >= 2 * 16 * 128 * 144) return;
    int half  = t / 294912;  int r1 = t % 294912;
    int chunk = r1 / 18432;  int r2 = r1 % 18432;
    int co_l  = r2 / 144;    int k  = r2 % 144;
    int dy = k / 48; int r3 = k % 48;
    int dx = r3 / 16; int cl = r3 % 16;
    int co = half * 128 + co_l;
    int ci = chunk * 16 + cl;
    g_wpk2[t] = __float2bfloat16(wv[((size_t)co * Cc + ci) * 9 + dy * 3 + dx]);
}

// ======================= K6: pipelined mma.sync bf16 implicit GEMM =======
// CTA: 128 co x 256 pixels (4 h x 64 w), 512 threads (16 warps, 4co x 4h).
// K = 2304 = 16 chunks x (3dy x 3dx x 16ci). Double-buffered smem.
// R buf:  6 planes x 48 k-rows x 144B          = 41472 B  (x2)
// As buf: 128 co x 304B (288 used)             = 38912 B  (x2)
#define R_KS     144
#define R_PLANE  (48 * R_KS)            // 6912
#define R_BUF    (6 * R_PLANE)          // 41472
#define AS_STRIDE 304
#define AS_BUF   (128 * AS_STRIDE)      // 38912
#define OFF_AS0  (2 * R_BUF)            // 82944
#define SMEM_DYN (2 * R_BUF + 2 * AS_BUF)   // 160768

__device__ __forceinline__ uint32_t smem_u32(const void* p) {
    uint32_t a;
    asm("{ .reg .u64 t; cvta.to.shared.u64 t, %1; cvt.u32.u64 %0, t; }" : "=r"(a) : "l"(p));
    return a;
}
__device__ __forceinline__ void ldmat_x4(uint32_t* r, uint32_t addr) {
    asm volatile("ldmatrix.sync.aligned.m8n8.x4.shared.b16 {%0,%1,%2,%3}, [%4];"
                 : "=r"(r[0]), "=r"(r[1]), "=r"(r[2]), "=r"(r[3]) : "r"(addr));
}
__device__ __forceinline__ void ldmat_x4_t(uint32_t* r, uint32_t addr) {
    asm volatile("ldmatrix.sync.aligned.m8n8.x4.trans.shared.b16 {%0,%1,%2,%3}, [%4];"
                 : "=r"(r[0]), "=r"(r[1]), "=r"(r[2]), "=r"(r[3]) : "r"(addr));
}
__device__ __forceinline__ void mma16816(float* c, const uint32_t* a, uint32_t b0, uint32_t b1) {
    asm volatile("mma.sync.aligned.m16n8k16.row.col.f32.bf16.bf16.f32 "
                 "{%0,%1,%2,%3}, {%4,%5,%6,%7}, {%8,%9}, {%0,%1,%2,%3};"
                 : "+f"(c[0]), "+f"(c[1]), "+f"(c[2]), "+f"(c[3])
                 : "r"(a[0]), "r"(a[1]), "r"(a[2]), "r"(a[3]), "r"(b0), "r"(b1));
}
__device__ __forceinline__ void cp16(uint32_t dst, const void* src) {
    asm volatile("cp.async.ca.shared.global [%0], [%1], 16;"
                 :: "r"(dst), "l"(src) : "memory");
}
__device__ __forceinline__ void cp_commit() { asm volatile("cp.async.commit_group;" ::: "memory"); }
__device__ __forceinline__ void cp_wait0()  { asm volatile("cp.async.wait_group 0;" ::: "memory"); }

__global__ void __launch_bounds__(512, 1) k_conv(
    const float* __restrict__ x,
    const float* __restrict__ gamma, const float* __restrict__ beta,
    const float* __restrict__ rmean, const float* __restrict__ rvar,
    float* __restrict__ out)
{
    extern __shared__ __align__(128) char smem[];
    uint32_t sb = smem_u32(smem);

    int tid  = threadIdx.x;
    int l    = tid & 31;
    int wid  = tid >> 5;             // 0..15
    int wm   = wid & 3;              // co group
    int wp   = tid >> 7;             // pixel (h) row 0..3

    int half = blockIdx.x;           // co half
    int co0  = half * 128;
    int b    = blockIdx.y >> 4;
    int h0   = (blockIdx.y & 15) << 2;

    const __nv_bfloat16* xbf = g_xbf + (size_t)b * Cc * Hh * Ww;

    // ldmatrix lane address components
    uint32_t kLane = (uint32_t)(((l >> 3) & 1) * 8 + (l & 7));
    uint32_t wLane = (uint32_t)((l >> 4) * 8);
    uint32_t aLane = (uint32_t)(wm * 32 + (l & 15)) * AS_STRIDE + ((l >> 4) * 8) * 2;
    uint32_t bLane = kLane * R_KS + wLane * 2;

    float acc[2][8][4];
    #pragma unroll
    for (int i = 0; i < 2; ++i)
        #pragma unroll
        for (int j = 0; j < 8; ++j)
            #pragma unroll
            for (int q = 0; q < 4; ++q) acc[i][j][q] = 0.f;

    // ---- staging helpers -------------------------------------------------
    // x loads: warp `wid` owns ci = wid; lane owns w-pair (2l, 2l+1); 6 rows.
    auto load_x = [&](int chunk, uint32_t* xr) {
        int ci = chunk * 16 + wid;
        const char* base = (const char*)(xbf + ((size_t)ci * Hh) * Ww) + 4 * l;
        #pragma unroll
        for (int it = 0; it < 6; ++it) {
            int h = h0 - 1 + it;
            uint32_t v = 0;
            if (h >= 0 && h < Hh)
                v = *reinterpret_cast<const uint32_t*>(base + h * (Ww * 2));
            xr[it] = v;
        }
    };
    auto sts_R = [&](uint32_t rbuf, const uint32_t* xr) {
        #pragma unroll
        for (int it = 0; it < 6; ++it) {
            uint32_t own  = xr[it];
            uint32_t prev = __shfl_up_sync(0xffffffffu, own, 1);
            uint32_t next = __shfl_down_sync(0xffffffffu, own, 1);
            if (l == 0)  prev = 0;
            if (l == 31) next = 0;
            uint32_t p0 = (prev >> 16) | (own << 16);   // plane dx=0: x[w-1]
            uint32_t p2 = (own >> 16) | (next << 16);   // plane dx=2: x[w+1]
            char* plane = smem + rbuf + it * R_PLANE + l * 4;
            *reinterpret_cast<uint32_t*>(plane + (wid)      * R_KS) = p0;
            *reinterpret_cast<uint32_t*>(plane + (16 + wid) * R_KS) = own;
            *reinterpret_cast<uint32_t*>(plane + (32 + wid) * R_KS) = p2;
        }
    };
    auto cp_As = [&](int chunk, uint32_t abuf) {
        const char* src = (const char*)g_wpk2
                        + ((size_t)(half * 16 + chunk) * 128) * 288;
        #pragma unroll
        for (int j = 0; j < 5; ++j) {
            int s = tid + j * 512;
            if (s < 2304) {
                int row = s / 18, c16 = s - row * 18;
                cp16(sb + abuf + row * AS_STRIDE + c16 * 16,
                     src + row * 288 + c16 * 16);
            }
        }
        cp_commit();
    };
    auto do_mma = [&](uint32_t rbuf, uint32_t abuf) {
        #pragma unroll
        for (int dy = 0; dy < 3; ++dy) {
            uint32_t bPlane = sb + rbuf + (uint32_t)(wp + dy) * R_PLANE + bLane;
            uint32_t aDy    = sb + abuf + aLane + (uint32_t)dy * 96;
            #pragma unroll
            for (int ks = 0; ks < 3; ++ks) {
                uint32_t a[2][4];
                uint32_t aAddr = aDy + (uint32_t)ks * 32;
                ldmat_x4(a[0], aAddr);
                ldmat_x4(a[1], aAddr + 16u * AS_STRIDE);
                uint32_t bf[4][4];
                uint32_t bAddr = bPlane + (uint32_t)(ks * 16) * R_KS;
                #pragma unroll
                for (int g = 0; g < 4; ++g)
                    ldmat_x4_t(bf[g], bAddr + (uint32_t)g * 32);
                #pragma unroll
                for (int mf = 0; mf < 2; ++mf)
                    #pragma unroll
                    for (int nf = 0; nf < 8; ++nf)
                        mma16816(acc[mf][nf], a[mf],
                                 bf[nf >> 1][(nf & 1) * 2], bf[nf >> 1][(nf & 1) * 2 + 1]);
            }
        }
    };

    // ---- prologue: stage chunk 0 into buffer 0 ---------------------------
    uint32_t xr[6];
    load_x(0, xr);
    cp_As(0, OFF_AS0);
    sts_R(0, xr);
    cp_wait0();
    __syncthreads();

    // ---- pipelined mainloop ---------------------------------------------
    for (int c = 0; c < 16; ++c) {
        uint32_t rcur = (uint32_t)(c & 1) * R_BUF;
        uint32_t acur = OFF_AS0 + (uint32_t)(c & 1) * AS_BUF;
        uint32_t rnxt = (uint32_t)((c + 1) & 1) * R_BUF;
        uint32_t anxt = OFF_AS0 + (uint32_t)((c + 1) & 1) * AS_BUF;
        if (c < 15) {
            load_x(c + 1, xr);       // long-latency LDGs issued first
            cp_As(c + 1, anxt);      // async weight slab
        }
        do_mma(rcur, acur);          // hides the latency above
        if (c < 15) {
            sts_R(rnxt, xr);
            cp_wait0();
            __syncthreads();
        }
    }

    // ---- epilogue: relu((scores*fv + x)*scale + bias) --------------------
    int h = h0 + wp;
    #pragma unroll
    for (int mf = 0; mf < 2; ++mf) {
        int coA = co0 + wm * 32 + mf * 16 + (l >> 2);
        int coB = coA + 8;
        float sA = g_scores[b * Cc + coA];
        float sB = g_scores[b * Cc + coB];
        float scA = gamma[coA] * rsqrtf(rvar[coA] + EPSf);
        float scB = gamma[coB] * rsqrtf(rvar[coB] + EPSf);
        float biA = beta[coA] - rmean[coA] * scA;
        float biB = beta[coB] - rmean[coB] * scB;
        const float* xrA = x + (((size_t)b * Cc + coA) * Hh + h) * Ww;
        const float* xrB = x + (((size_t)b * Cc + coB) * Hh + h) * Ww;
        float* oA = out + (((size_t)b * Cc + coA) * Hh + h) * Ww;
        float* oB = out + (((size_t)b * Cc + coB) * Hh + h) * Ww;
        #pragma unroll
        for (int nf = 0; nf < 8; ++nf) {
            int w = nf * 8 + (l & 3) * 2;
            float2 xvA = *reinterpret_cast<const float2*>(xrA + w);
            float2 xvB = *reinterpret_cast<const float2*>(xrB + w);
            float2 o0, o1;
            o0.x = fmaxf((sA * acc[mf][nf][0] + xvA.x) * scA + biA, 0.f);
            o0.y = fmaxf((sA * acc[mf][nf][1] + xvA.y) * scA + biA, 0.f);
            o1.x = fmaxf((sB * acc[mf][nf][2] + xvB.x) * scB + biB, 0.f);
            o1.y = fmaxf((sB * acc[mf][nf][3] + xvB.y) * scB + biB, 0.f);
            *reinterpret_cast<float2*>(oA + w) = o0;
            *reinterpret_cast<float2*>(oB + w) = o1;
        }
    }
}

// ---------------- launch --------------------------------------------------
extern "C" void kernel_launch(void* const* d_in, const int* in_sizes, int n_in,
                              void* d_out, int out_size)
{
    const float* x     = (const float*)d_in[0];
    const float* wq    = (const float*)d_in[1];
    const float* wk    = (const float*)d_in[2];
    const float* wv    = (const float*)d_in[3];
    const float* gamma = (const float*)d_in[4];
    const float* beta  = (const float*)d_in[5];
    const float* rmean = (const float*)d_in[6];
    const float* rvar  = (const float*)d_in[7];
    float* out = (float*)d_out;
    (void)in_sizes; (void)n_in; (void)out_size;

    cudaFuncSetAttribute(k_conv, cudaFuncAttributeMaxDynamicSharedMemorySize, SMEM_DYN);

    k_colsum<<<Bb * Cc, 64>>>(x);
    k_wksum<<<(K9 + 255) / 256, 256>>>(wk);
    k_wpack2<<<(2*16*128*144 + 255) / 256, 256>>>(wv);
    k_ksum<<<dim3(Ww, Bb), 256>>>();
    k_G<<<dim3(Cc, Bb), 288>>>();
    k_fscore<<<Cc, 256>>>(wq);
    k_softmax<<<Bb, 256>>>();
    k_conv<<<dim3(2, 256), 512, SMEM_DYN>>>(x, gamma, beta, rmean, rvar, out);
}